// round 2
// baseline (speedup 1.0000x reference)
#include <cuda_runtime.h>
#include <cuda_bf16.h>
#include <cstdint>

#define IN_F   8192
#define OUT_F  8192
#define NBLK   64
#define MTILES 64

// smem: bias 512B, then 4 bf16 tiles 128 rows x 136 halves (272B stride)
#define ROW_B   272
#define TILE_B  (128 * ROW_B)        // 34816
#define OFF_BIAS 0
#define OFF_XH  512
#define OFF_XL  (512 + TILE_B)       // 35328
#define OFF_WH  (512 + 2 * TILE_B)   // 70144
#define OFF_WL  (512 + 3 * TILE_B)   // 104960
#define SMEM_TOTAL (512 + 4 * TILE_B) // 139776

__device__ __forceinline__ uint32_t smem_u32(const void* p) {
    uint32_t a;
    asm("{ .reg .u64 t; cvta.to.shared.u64 t, %1; cvt.u32.u64 %0, t; }" : "=r"(a) : "l"(p));
    return a;
}

__device__ __forceinline__ uint32_t pack_bf2(float a, float b) {
    __nv_bfloat162 h = __float22bfloat162_rn(make_float2(a, b));
    return *reinterpret_cast<uint32_t*>(&h);
}

__device__ __forceinline__ void ldsm_x4(uint32_t& r0, uint32_t& r1, uint32_t& r2, uint32_t& r3,
                                        uint32_t addr) {
    asm volatile("ldmatrix.sync.aligned.m8n8.x4.shared.b16 {%0,%1,%2,%3}, [%4];"
                 : "=r"(r0), "=r"(r1), "=r"(r2), "=r"(r3) : "r"(addr));
}

__device__ __forceinline__ void mma_bf16(float* d, const uint32_t* a, uint32_t b0, uint32_t b1) {
    asm volatile(
        "mma.sync.aligned.m16n8k16.row.col.f32.bf16.bf16.f32 "
        "{%0,%1,%2,%3}, {%4,%5,%6,%7}, {%8,%9}, {%0,%1,%2,%3};"
        : "+f"(d[0]), "+f"(d[1]), "+f"(d[2]), "+f"(d[3])
        : "r"(a[0]), "r"(a[1]), "r"(a[2]), "r"(a[3]), "r"(b0), "r"(b1));
}

// Wire activation: sin(30 z) * exp(-(0.1 z)^2)
__device__ __forceinline__ float wire_act(float z) {
    float s, e;
    asm("sin.approx.ftz.f32 %0, %1;" : "=f"(s) : "f"(z * 30.0f));
    float t = -0.01442695040888963f * z * z;   // -0.01 * log2(e) * z^2
    asm("ex2.approx.ftz.f32 %0, %1;" : "=f"(e) : "f"(t));
    return s * e;
}

__global__ void __launch_bounds__(256, 1)
siren_blockdiag_mma_kernel(const float* __restrict__ x, const float* __restrict__ w,
                           const float* __restrict__ bias, float* __restrict__ out)
{
    extern __shared__ char smem[];
    const uint32_t sbase = smem_u32(smem);
    const int tid = threadIdx.x;
    const int wid = tid >> 5;
    const int lid = tid & 31;
    const int b  = blockIdx.x;   // feature block 0..63
    const int mt = blockIdx.y;   // token tile 0..63

    // ---- stage bias ----
    if (tid < 128) ((float*)(smem + OFF_BIAS))[tid] = bias[b * 128 + tid];

    // ---- stage X tile -> bf16 hi/lo ----
    {
        const float* xrow = x + (size_t)(mt * 128) * IN_F + (size_t)b * 128;
        #pragma unroll 4
        for (int i = tid; i < 4096; i += 256) {
            int r = i >> 5, c4 = i & 31;
            float4 v = *(const float4*)(xrow + (size_t)r * IN_F + (c4 << 2));
            uint32_t h01 = pack_bf2(v.x, v.y);
            uint32_t h23 = pack_bf2(v.z, v.w);
            __nv_bfloat162 hh01 = *reinterpret_cast<__nv_bfloat162*>(&h01);
            __nv_bfloat162 hh23 = *reinterpret_cast<__nv_bfloat162*>(&h23);
            uint32_t l01 = pack_bf2(v.x - __bfloat162float(hh01.x), v.y - __bfloat162float(hh01.y));
            uint32_t l23 = pack_bf2(v.z - __bfloat162float(hh23.x), v.w - __bfloat162float(hh23.y));
            uint32_t off = r * ROW_B + (c4 << 3);
            *(uint2*)(smem + OFF_XH + off) = make_uint2(h01, h23);
            *(uint2*)(smem + OFF_XL + off) = make_uint2(l01, l23);
        }
    }
    // ---- stage W block -> bf16 hi/lo ----
    {
        const float* wrow = w + (size_t)(b * 128) * IN_F + (size_t)b * 128;
        #pragma unroll 4
        for (int i = tid; i < 4096; i += 256) {
            int r = i >> 5, c4 = i & 31;
            float4 v = *(const float4*)(wrow + (size_t)r * IN_F + (c4 << 2));
            uint32_t h01 = pack_bf2(v.x, v.y);
            uint32_t h23 = pack_bf2(v.z, v.w);
            __nv_bfloat162 hh01 = *reinterpret_cast<__nv_bfloat162*>(&h01);
            __nv_bfloat162 hh23 = *reinterpret_cast<__nv_bfloat162*>(&h23);
            uint32_t l01 = pack_bf2(v.x - __bfloat162float(hh01.x), v.y - __bfloat162float(hh01.y));
            uint32_t l23 = pack_bf2(v.z - __bfloat162float(hh23.x), v.w - __bfloat162float(hh23.y));
            uint32_t off = r * ROW_B + (c4 << 3);
            *(uint2*)(smem + OFF_WH + off) = make_uint2(h01, h23);
            *(uint2*)(smem + OFF_WL + off) = make_uint2(l01, l23);
        }
    }
    __syncthreads();

    // ---- warp tiling: 8 warps -> 4 (m) x 2 (n); 32 rows x 64 cols per warp ----
    const int warp_m = wid & 3;
    const int warp_n = wid >> 2;
    const int M0 = warp_m * 32;
    const int N0 = warp_n * 64;

    // per-lane ldmatrix row offsets
    const uint32_t offA = (uint32_t)((lid & 15) * ROW_B + (lid >> 4) * 16);
    const uint32_t offB = (uint32_t)((((lid >> 4) & 1) * 8 + (lid & 7)) * ROW_B
                                     + ((lid >> 3) & 1) * 16);

    float acc[2][8][4];
    #pragma unroll
    for (int i = 0; i < 2; i++)
        #pragma unroll
        for (int j = 0; j < 8; j++)
            #pragma unroll
            for (int k = 0; k < 4; k++) acc[i][j][k] = 0.0f;

    const uint32_t abases[3] = { sbase + OFF_XH, sbase + OFF_XH, sbase + OFF_XL };
    const uint32_t bbases[3] = { sbase + OFF_WH, sbase + OFF_WL, sbase + OFF_WH };

    #pragma unroll
    for (int c = 0; c < 3; c++) {
        const uint32_t aB = abases[c] + (uint32_t)(M0 * ROW_B) + offA;
        const uint32_t bB = bbases[c] + (uint32_t)(N0 * ROW_B) + offB;
        #pragma unroll
        for (int ks = 0; ks < 8; ks++) {
            const uint32_t kb = (uint32_t)(ks * 32);
            uint32_t a0[4], a1[4];
            ldsm_x4(a0[0], a0[1], a0[2], a0[3], aB + kb);
            ldsm_x4(a1[0], a1[1], a1[2], a1[3], aB + kb + 16 * ROW_B);
            uint32_t bf[4][4];
            #pragma unroll
            for (int nt4 = 0; nt4 < 4; nt4++)
                ldsm_x4(bf[nt4][0], bf[nt4][1], bf[nt4][2], bf[nt4][3],
                        bB + kb + (uint32_t)(nt4 * 16 * ROW_B));
            #pragma unroll
            for (int nt = 0; nt < 8; nt++) {
                const uint32_t b0 = bf[nt >> 1][(nt & 1) * 2 + 0];
                const uint32_t b1 = bf[nt >> 1][(nt & 1) * 2 + 1];
                mma_bf16(acc[0][nt], a0, b0, b1);
                mma_bf16(acc[1][nt], a1, b0, b1);
            }
        }
    }

    // ---- epilogue: bias + wire activation + store ----
    const float* bs = (const float*)(smem + OFF_BIAS);
    const int lrow = lid >> 2;          // 0..7
    const int lcol = (lid & 3) * 2;     // 0,2,4,6
    #pragma unroll
    for (int m2 = 0; m2 < 2; m2++) {
        const int rbase = M0 + m2 * 16 + lrow;
        #pragma unroll
        for (int nt = 0; nt < 8; nt++) {
            const int nn = N0 + nt * 8 + lcol;
            float* p0 = out + (size_t)(mt * 128 + rbase) * OUT_F + (size_t)b * 128 + nn;
            float2 v0, v1;
            v0.x = wire_act(acc[m2][nt][0] + bs[nn]);
            v0.y = wire_act(acc[m2][nt][1] + bs[nn + 1]);
            v1.x = wire_act(acc[m2][nt][2] + bs[nn]);
            v1.y = wire_act(acc[m2][nt][3] + bs[nn + 1]);
            *(float2*)p0 = v0;
            *(float2*)(p0 + (size_t)8 * OUT_F) = v1;
        }
    }
}

extern "C" void kernel_launch(void* const* d_in, const int* in_sizes, int n_in,
                              void* d_out, int out_size)
{
    const float* x    = (const float*)d_in[0];
    const float* w    = (const float*)d_in[1];
    const float* bias = (const float*)d_in[2];
    float* out = (float*)d_out;

    cudaFuncSetAttribute(siren_blockdiag_mma_kernel,
                         cudaFuncAttributeMaxDynamicSharedMemorySize, SMEM_TOTAL);
    dim3 grid(NBLK, MTILES);
    siren_blockdiag_mma_kernel<<<grid, 256, SMEM_TOTAL>>>(x, w, bias, out);
}

// round 5
// speedup vs baseline: 1.1238x; 1.1238x over previous
#include <cuda_runtime.h>
#include <cuda_bf16.h>
#include <cstdint>

#define IN_F   8192
#define OUT_F  8192
#define NBLK   64
#define MT_ROWS 64
#define MTILES 128            // 8192 tokens / 64

#define ROW_B   272           // padded row stride (136 bf16)
#define TILE_WB (128 * ROW_B) // 34816
#define TILE_XB (MT_ROWS * ROW_B) // 17408

#define OFF_BIAS 0
#define OFF_XH  512
#define OFF_XL  (512 + TILE_XB)                  // 17920
#define OFF_WH  (512 + 2 * TILE_XB)              // 35328
#define OFF_WL  (512 + 2 * TILE_XB + TILE_WB)    // 70144  (contiguous after WH)
#define SMEM_TOTAL (512 + 2 * TILE_XB + 2 * TILE_WB) // 104960

// pre-converted W: [b][hi tile 34816B][lo tile 34816B]
__device__ __align__(16) char g_wcvt[NBLK * 2 * TILE_WB];

__device__ __forceinline__ uint32_t smem_u32(const void* p) {
    uint32_t a;
    asm("{ .reg .u64 t; cvta.to.shared.u64 t, %1; cvt.u32.u64 %0, t; }" : "=r"(a) : "l"(p));
    return a;
}
__device__ __forceinline__ uint32_t pack_bf2(float a, float b) {
    __nv_bfloat162 h = __float22bfloat162_rn(make_float2(a, b));
    return *reinterpret_cast<uint32_t*>(&h);
}
__device__ __forceinline__ void ldsm_x4(uint32_t& r0, uint32_t& r1, uint32_t& r2, uint32_t& r3,
                                        uint32_t addr) {
    asm volatile("ldmatrix.sync.aligned.m8n8.x4.shared.b16 {%0,%1,%2,%3}, [%4];"
                 : "=r"(r0), "=r"(r1), "=r"(r2), "=r"(r3) : "r"(addr));
}
__device__ __forceinline__ void mma_bf16(float* d, const uint32_t* a, uint32_t b0, uint32_t b1) {
    asm volatile(
        "mma.sync.aligned.m16n8k16.row.col.f32.bf16.bf16.f32 "
        "{%0,%1,%2,%3}, {%4,%5,%6,%7}, {%8,%9}, {%0,%1,%2,%3};"
        : "+f"(d[0]), "+f"(d[1]), "+f"(d[2]), "+f"(d[3])
        : "r"(a[0]), "r"(a[1]), "r"(a[2]), "r"(a[3]), "r"(b0), "r"(b1));
}
__device__ __forceinline__ float wire_act(float z) {
    float s, e;
    asm("sin.approx.ftz.f32 %0, %1;" : "=f"(s) : "f"(z * 30.0f));
    float t = -0.01442695040888963f * z * z;   // -0.01 * log2(e) * z^2
    asm("ex2.approx.ftz.f32 %0, %1;" : "=f"(e) : "f"(t));
    return s * e;
}

// ---------------- prep: convert W blocks to bf16 hi/lo tiles ----------------
__global__ void __launch_bounds__(128)
wcvt_kernel(const float* __restrict__ w)
{
    const int b = blockIdx.x;
    const int t = threadIdx.x;
    const int r0 = t >> 5;
    const int c4 = t & 31;
    const float* wrow = w + (size_t)(b * 128) * IN_F + (size_t)b * 128;
    char* dstH = g_wcvt + (size_t)b * (2 * TILE_WB);
    char* dstL = dstH + TILE_WB;
    #pragma unroll 4
    for (int r = r0; r < 128; r += 4) {
        float4 v = *(const float4*)(wrow + (size_t)r * IN_F + (c4 << 2));
        uint32_t h01 = pack_bf2(v.x, v.y);
        uint32_t h23 = pack_bf2(v.z, v.w);
        __nv_bfloat162 hh01 = *reinterpret_cast<__nv_bfloat162*>(&h01);
        __nv_bfloat162 hh23 = *reinterpret_cast<__nv_bfloat162*>(&h23);
        uint32_t l01 = pack_bf2(v.x - __bfloat162float(hh01.x), v.y - __bfloat162float(hh01.y));
        uint32_t l23 = pack_bf2(v.z - __bfloat162float(hh23.x), v.w - __bfloat162float(hh23.y));
        uint32_t off = (uint32_t)(r * ROW_B + (c4 << 3));
        *(uint2*)(dstH + off) = make_uint2(h01, h23);
        *(uint2*)(dstL + off) = make_uint2(l01, l23);
    }
}

// ---------------- main kernel ----------------
__global__ void __launch_bounds__(128, 2)
siren_blockdiag_mma2_kernel(const float* __restrict__ x, const float* __restrict__ bias,
                            float* __restrict__ out)
{
    extern __shared__ char smem[];
    const uint32_t sbase = smem_u32(smem);
    const int tid = threadIdx.x;
    const int wid = tid >> 5;
    const int lid = tid & 31;
    const int mt = blockIdx.x;   // token tile 0..127 (64 rows each)
    const int b  = blockIdx.y;   // feature block 0..63

    // ---- W tiles via cp.async (pre-converted, identical layout) ----
    {
        const char* wsrc = g_wcvt + (size_t)b * (2 * TILE_WB);
        #pragma unroll 8
        for (int i = tid; i < (2 * TILE_WB) / 16; i += 128) {
            uint32_t dst = sbase + OFF_WH + i * 16;
            asm volatile("cp.async.cg.shared.global [%0], [%1], 16;"
                         :: "r"(dst), "l"(wsrc + i * 16) : "memory");
        }
        asm volatile("cp.async.commit_group;" ::: "memory");
    }

    // ---- bias ----
    ((float*)(smem + OFF_BIAS))[tid] = bias[b * 128 + tid];

    // ---- X tile -> bf16 hi/lo (64 rows x 128 cols) ----
    {
        const float* xrow = x + (size_t)(mt * MT_ROWS) * IN_F + (size_t)b * 128;
        #pragma unroll 4
        for (int i = tid; i < MT_ROWS * 32; i += 128) {
            int r = i >> 5, c4 = i & 31;
            float4 v = *(const float4*)(xrow + (size_t)r * IN_F + (c4 << 2));
            uint32_t h01 = pack_bf2(v.x, v.y);
            uint32_t h23 = pack_bf2(v.z, v.w);
            __nv_bfloat162 hh01 = *reinterpret_cast<__nv_bfloat162*>(&h01);
            __nv_bfloat162 hh23 = *reinterpret_cast<__nv_bfloat162*>(&h23);
            uint32_t l01 = pack_bf2(v.x - __bfloat162float(hh01.x), v.y - __bfloat162float(hh01.y));
            uint32_t l23 = pack_bf2(v.z - __bfloat162float(hh23.x), v.w - __bfloat162float(hh23.y));
            uint32_t off = (uint32_t)(r * ROW_B + (c4 << 3));
            *(uint2*)(smem + OFF_XH + off) = make_uint2(h01, h23);
            *(uint2*)(smem + OFF_XL + off) = make_uint2(l01, l23);
        }
    }

    asm volatile("cp.async.wait_group 0;" ::: "memory");
    __syncthreads();

    // ---- warp tiling: 4 warps -> 2 (m) x 2 (n); 32 rows x 64 cols per warp ----
    const int warp_m = wid & 1;
    const int warp_n = wid >> 1;
    const int M0 = warp_m * 32;
    const int N0 = warp_n * 64;

    const uint32_t offA = (uint32_t)((lid & 15) * ROW_B + (lid >> 4) * 16);
    const uint32_t offB = (uint32_t)((((lid >> 4) & 1) * 8 + (lid & 7)) * ROW_B
                                     + ((lid >> 3) & 1) * 16);

    float acc[2][8][4];
    #pragma unroll
    for (int i = 0; i < 2; i++)
        #pragma unroll
        for (int j = 0; j < 8; j++)
            #pragma unroll
            for (int k = 0; k < 4; k++) acc[i][j][k] = 0.0f;

    const uint32_t abases[3] = { sbase + OFF_XH, sbase + OFF_XH, sbase + OFF_XL };
    const uint32_t bbases[3] = { sbase + OFF_WH, sbase + OFF_WL, sbase + OFF_WH };

    #pragma unroll
    for (int c = 0; c < 3; c++) {
        const uint32_t aB = abases[c] + (uint32_t)(M0 * ROW_B) + offA;
        const uint32_t bB = bbases[c] + (uint32_t)(N0 * ROW_B) + offB;
        #pragma unroll
        for (int ks = 0; ks < 8; ks++) {
            const uint32_t kb = (uint32_t)(ks * 32);
            uint32_t a0[4], a1[4];
            ldsm_x4(a0[0], a0[1], a0[2], a0[3], aB + kb);
            ldsm_x4(a1[0], a1[1], a1[2], a1[3], aB + kb + 16 * ROW_B);
            uint32_t bf[4][4];
            #pragma unroll
            for (int nt4 = 0; nt4 < 4; nt4++)
                ldsm_x4(bf[nt4][0], bf[nt4][1], bf[nt4][2], bf[nt4][3],
                        bB + kb + (uint32_t)(nt4 * 16 * ROW_B));
            #pragma unroll
            for (int nt = 0; nt < 8; nt++) {
                const uint32_t b0 = bf[nt >> 1][(nt & 1) * 2 + 0];
                const uint32_t b1 = bf[nt >> 1][(nt & 1) * 2 + 1];
                mma_bf16(acc[0][nt], a0, b0, b1);
                mma_bf16(acc[1][nt], a1, b0, b1);
            }
        }
    }

    // ---- epilogue: bias + wire activation + store ----
    const float* bs = (const float*)(smem + OFF_BIAS);
    const int lrow = lid >> 2;
    const int lcol = (lid & 3) * 2;
    #pragma unroll
    for (int m2 = 0; m2 < 2; m2++) {
        const int rbase = M0 + m2 * 16 + lrow;
        #pragma unroll
        for (int nt = 0; nt < 8; nt++) {
            const int nn = N0 + nt * 8 + lcol;
            float* p0 = out + (size_t)(mt * MT_ROWS + rbase) * OUT_F + (size_t)b * 128 + nn;
            float2 v0, v1;
            v0.x = wire_act(acc[m2][nt][0] + bs[nn]);
            v0.y = wire_act(acc[m2][nt][1] + bs[nn + 1]);
            v1.x = wire_act(acc[m2][nt][2] + bs[nn]);
            v1.y = wire_act(acc[m2][nt][3] + bs[nn + 1]);
            *(float2*)p0 = v0;
            *(float2*)(p0 + (size_t)8 * OUT_F) = v1;
        }
    }
}

extern "C" void kernel_launch(void* const* d_in, const int* in_sizes, int n_in,
                              void* d_out, int out_size)
{
    const float* x    = (const float*)d_in[0];
    const float* w    = (const float*)d_in[1];
    const float* bias = (const float*)d_in[2];
    float* out = (float*)d_out;

    wcvt_kernel<<<NBLK, 128>>>(w);

    cudaFuncSetAttribute(siren_blockdiag_mma2_kernel,
                         cudaFuncAttributeMaxDynamicSharedMemorySize, SMEM_TOTAL);
    dim3 grid(MTILES, NBLK);
    siren_blockdiag_mma2_kernel<<<grid, 128, SMEM_TOTAL>>>(x, bias, out);
}

// round 6
// speedup vs baseline: 1.2346x; 1.0986x over previous
#include <cuda_runtime.h>
#include <cuda_fp16.h>
#include <cstdint>

#define IN_F   8192
#define OUT_F  8192
#define NBLK   64
#define M_TILE 64
#define TPC    4            // tiles per CTA
#define GRID_Y 32           // 32*4 tiles * 64 rows = 8192 tokens

#define ROW_B   272         // padded row stride bytes (136 halves)
#define TILE_HB (M_TILE * ROW_B)    // 17408: one 64x128 fp16 tile
#define XSET_B  (2 * TILE_HB)       // 34816: Xh + Xl
#define W_B     (128 * ROW_B)       // 34816: 128x128 fp16 W tile

#define OFF_BIAS 0
#define OFF_MBAR 512                 // full0@512 empty0@520 full1@528 empty1@536
#define OFF_W    1024
#define OFF_X    (1024 + W_B)        // 35840
#define SMEM_TOTAL (OFF_X + 2 * XSET_B)   // 105472 -> 2 CTAs/SM

// pre-converted W blocks: [b] -> 128x128 fp16 padded tile
__device__ __align__(16) char g_wcvt[NBLK * W_B];

__device__ __forceinline__ uint32_t smem_u32(const void* p) {
    uint32_t a;
    asm("{ .reg .u64 t; cvta.to.shared.u64 t, %1; cvt.u32.u64 %0, t; }" : "=r"(a) : "l"(p));
    return a;
}
__device__ __forceinline__ uint32_t pack_h2(float a, float b) {
    __half2 h = __float22half2_rn(make_float2(a, b));
    return *reinterpret_cast<uint32_t*>(&h);
}
__device__ __forceinline__ void ldsm_x4(uint32_t& r0, uint32_t& r1, uint32_t& r2, uint32_t& r3,
                                        uint32_t addr) {
    asm volatile("ldmatrix.sync.aligned.m8n8.x4.shared.b16 {%0,%1,%2,%3}, [%4];"
                 : "=r"(r0), "=r"(r1), "=r"(r2), "=r"(r3) : "r"(addr));
}
__device__ __forceinline__ void mma_f16(float* d, const uint32_t* a, uint32_t b0, uint32_t b1) {
    asm volatile(
        "mma.sync.aligned.m16n8k16.row.col.f32.f16.f16.f32 "
        "{%0,%1,%2,%3}, {%4,%5,%6,%7}, {%8,%9}, {%0,%1,%2,%3};"
        : "+f"(d[0]), "+f"(d[1]), "+f"(d[2]), "+f"(d[3])
        : "r"(a[0]), "r"(a[1]), "r"(a[2]), "r"(a[3]), "r"(b0), "r"(b1));
}
__device__ __forceinline__ float wire_act(float z) {
    float s, e;
    asm("sin.approx.ftz.f32 %0, %1;" : "=f"(s) : "f"(z * 30.0f));
    float t = -0.01442695040888963f * z * z;   // -0.01 * log2(e) * z^2
    asm("ex2.approx.ftz.f32 %0, %1;" : "=f"(e) : "f"(t));
    return s * e;
}

#define MBAR_INIT(mb, c) asm volatile("mbarrier.init.shared.b64 [%0], %1;" :: "r"(mb), "r"((uint32_t)(c)) : "memory")
#define MBAR_ARRIVE(mb)  asm volatile("mbarrier.arrive.shared.b64 _, [%0];" :: "r"(mb) : "memory")
__device__ __forceinline__ void mbar_wait(uint32_t mb, uint32_t parity) {
    uint32_t done = 0;
    while (!done) {
        asm volatile(
            "{\n\t.reg .pred p;\n\t"
            "mbarrier.try_wait.parity.acquire.cta.shared::cta.b64 p, [%1], %2, 0x989680;\n\t"
            "selp.b32 %0, 1, 0, p;\n\t}"
            : "=r"(done) : "r"(mb), "r"(parity) : "memory");
    }
}

// ------------- prep: convert W diag blocks to fp16 padded tiles -------------
__global__ void __launch_bounds__(128)
wcvt_kernel(const float* __restrict__ w)
{
    const int b = blockIdx.x;
    const int t = threadIdx.x;
    const int r0 = t >> 5;
    const int c4 = t & 31;
    const float* wrow = w + (size_t)(b * 128) * IN_F + (size_t)b * 128;
    char* dst = g_wcvt + (size_t)b * W_B;
    #pragma unroll 4
    for (int r = r0; r < 128; r += 4) {
        float4 v = *(const float4*)(wrow + (size_t)r * IN_F + (c4 << 2));
        uint32_t h01 = pack_h2(v.x, v.y);
        uint32_t h23 = pack_h2(v.z, v.w);
        *(uint2*)(dst + r * ROW_B + (c4 << 3)) = make_uint2(h01, h23);
    }
}

// ------------- main kernel: warp-specialized pipelined GEMM -------------
__global__ void __launch_bounds__(192, 2)
siren_pipe_kernel(const float* __restrict__ x, const float* __restrict__ bias,
                  float* __restrict__ out)
{
    extern __shared__ char smem[];
    const uint32_t sbase = smem_u32(smem);
    const int tid = threadIdx.x;
    const int wid = tid >> 5;
    const int lid = tid & 31;
    const int b = blockIdx.x;

    // mbarriers: full[s] (64 producer arrivals), empty[s] (128 consumer arrivals)
    if (tid == 0) {
        MBAR_INIT(sbase + OFF_MBAR + 0, 64);    // full0
        MBAR_INIT(sbase + OFF_MBAR + 8, 128);   // empty0
        MBAR_INIT(sbase + OFF_MBAR + 16, 64);   // full1
        MBAR_INIT(sbase + OFF_MBAR + 24, 128);  // empty1
    }
    __syncthreads();

    if (wid >= 4) {
        // ================= PRODUCER (warps 4,5 = 64 threads) =================
        const int pt = tid - 128;               // 0..63
        int stage = 0, phase = 1;               // first empty-wait passes immediately
        #pragma unroll 1
        for (int i = 0; i < TPC; i++) {
            const int s = stage;
            mbar_wait(sbase + OFF_MBAR + s * 16 + 8, phase);
            const int row0 = (blockIdx.y * TPC + i) * M_TILE;
            const float* xp = x + (size_t)row0 * IN_F + (size_t)b * 128;
            char* dstH = smem + OFF_X + s * XSET_B;
            char* dstL = dstH + TILE_HB;
            #pragma unroll 4
            for (int j = 0; j < 32; j++) {
                const int item = pt + 64 * j;
                const int r = item >> 5, c4 = item & 31;
                float4 v = *(const float4*)(xp + (size_t)r * IN_F + (c4 << 2));
                uint32_t h01 = pack_h2(v.x, v.y);
                uint32_t h23 = pack_h2(v.z, v.w);
                __half2 hh01 = *reinterpret_cast<__half2*>(&h01);
                __half2 hh23 = *reinterpret_cast<__half2*>(&h23);
                uint32_t l01 = pack_h2(v.x - __half2float(hh01.x), v.y - __half2float(hh01.y));
                uint32_t l23 = pack_h2(v.z - __half2float(hh23.x), v.w - __half2float(hh23.y));
                const uint32_t off = (uint32_t)(r * ROW_B + (c4 << 3));
                *(uint2*)(dstH + off) = make_uint2(h01, h23);
                *(uint2*)(dstL + off) = make_uint2(l01, l23);
            }
            MBAR_ARRIVE(sbase + OFF_MBAR + s * 16);   // full[s]
            if (++stage == 2) { stage = 0; phase ^= 1; }
        }
    } else {
        // ================= CONSUMER (warps 0-3 = 128 threads) =================
        // one-time: W tile via cp.async + bias
        {
            const char* wsrc = g_wcvt + (size_t)b * W_B;
            #pragma unroll 17
            for (int i = tid; i < W_B / 16; i += 128) {
                uint32_t dst = sbase + OFF_W + i * 16;
                asm volatile("cp.async.cg.shared.global [%0], [%1], 16;"
                             :: "r"(dst), "l"(wsrc + i * 16) : "memory");
            }
            asm volatile("cp.async.commit_group;" ::: "memory");
            ((float*)(smem + OFF_BIAS))[tid] = bias[b * 128 + tid];
            asm volatile("cp.async.wait_group 0;" ::: "memory");
            asm volatile("bar.sync 1, 128;" ::: "memory");   // consumer-only barrier
        }

        const int warp_m = wid & 1;
        const int warp_n = wid >> 1;
        const int M0 = warp_m * 32;
        const int N0 = warp_n * 64;
        const uint32_t offA = (uint32_t)((lid & 15) * ROW_B + (lid >> 4) * 16);
        const uint32_t offB = (uint32_t)((((lid >> 4) & 1) * 8 + (lid & 7)) * ROW_B
                                         + ((lid >> 3) & 1) * 16);
        const uint32_t bB = sbase + OFF_W + (uint32_t)(N0 * ROW_B) + offB;
        const float* bs = (const float*)(smem + OFF_BIAS);
        const int lrow = lid >> 2;
        const int lcol = (lid & 3) * 2;

        int stage = 0, phase = 0;
        #pragma unroll 1
        for (int i = 0; i < TPC; i++) {
            const int s = stage;
            mbar_wait(sbase + OFF_MBAR + s * 16, phase);   // full[s]

            const uint32_t aH = sbase + OFF_X + s * XSET_B + (uint32_t)(M0 * ROW_B) + offA;
            const uint32_t aL = aH + TILE_HB;

            float acc[2][8][4];
            #pragma unroll
            for (int m2 = 0; m2 < 2; m2++)
                #pragma unroll
                for (int nt = 0; nt < 8; nt++)
                    #pragma unroll
                    for (int k = 0; k < 4; k++) acc[m2][nt][k] = 0.0f;

            #pragma unroll
            for (int ks = 0; ks < 8; ks++) {
                const uint32_t kb = (uint32_t)(ks * 32);
                uint32_t bf[4][4];
                #pragma unroll
                for (int nt4 = 0; nt4 < 4; nt4++)
                    ldsm_x4(bf[nt4][0], bf[nt4][1], bf[nt4][2], bf[nt4][3],
                            bB + kb + (uint32_t)(nt4 * 16 * ROW_B));
                uint32_t ah0[4], ah1[4], al0[4], al1[4];
                ldsm_x4(ah0[0], ah0[1], ah0[2], ah0[3], aH + kb);
                ldsm_x4(ah1[0], ah1[1], ah1[2], ah1[3], aH + kb + 16 * ROW_B);
                ldsm_x4(al0[0], al0[1], al0[2], al0[3], aL + kb);
                ldsm_x4(al1[0], al1[1], al1[2], al1[3], aL + kb + 16 * ROW_B);
                #pragma unroll
                for (int nt = 0; nt < 8; nt++) {
                    const uint32_t b0 = bf[nt >> 1][(nt & 1) * 2 + 0];
                    const uint32_t b1 = bf[nt >> 1][(nt & 1) * 2 + 1];
                    mma_f16(acc[0][nt], ah0, b0, b1);
                    mma_f16(acc[1][nt], ah1, b0, b1);
                    mma_f16(acc[0][nt], al0, b0, b1);
                    mma_f16(acc[1][nt], al1, b0, b1);
                }
            }
            MBAR_ARRIVE(sbase + OFF_MBAR + s * 16 + 8);    // empty[s] — free buffer early

            // epilogue
            const int row0 = (blockIdx.y * TPC + i) * M_TILE;
            #pragma unroll
            for (int m2 = 0; m2 < 2; m2++) {
                const int rbase = row0 + M0 + m2 * 16 + lrow;
                #pragma unroll
                for (int nt = 0; nt < 8; nt++) {
                    const int nn = N0 + nt * 8 + lcol;
                    float* p0 = out + (size_t)rbase * OUT_F + (size_t)b * 128 + nn;
                    float2 v0, v1;
                    v0.x = wire_act(acc[m2][nt][0] + bs[nn]);
                    v0.y = wire_act(acc[m2][nt][1] + bs[nn + 1]);
                    v1.x = wire_act(acc[m2][nt][2] + bs[nn]);
                    v1.y = wire_act(acc[m2][nt][3] + bs[nn + 1]);
                    *(float2*)p0 = v0;
                    *(float2*)(p0 + (size_t)8 * OUT_F) = v1;
                }
            }
            if (++stage == 2) { stage = 0; phase ^= 1; }
        }
    }
}

extern "C" void kernel_launch(void* const* d_in, const int* in_sizes, int n_in,
                              void* d_out, int out_size)
{
    const float* x    = (const float*)d_in[0];
    const float* w    = (const float*)d_in[1];
    const float* bias = (const float*)d_in[2];
    float* out = (float*)d_out;

    wcvt_kernel<<<NBLK, 128>>>(w);

    cudaFuncSetAttribute(siren_pipe_kernel,
                         cudaFuncAttributeMaxDynamicSharedMemorySize, SMEM_TOTAL);
    dim3 grid(NBLK, GRID_Y);
    siren_pipe_kernel<<<grid, 192, SMEM_TOTAL>>>(x, bias, out);
}

// round 7
// speedup vs baseline: 1.6785x; 1.3595x over previous
#include <cuda_runtime.h>
#include <cuda_fp16.h>
#include <cstdint>

#define IN_F   8192
#define OUT_F  8192
#define NBLK   64
#define M_TILE 64
#define TPC    8            // tiles per CTA
#define GRID_Y 16           // 16*8 tiles * 64 rows = 8192 tokens

#define ROW_B   272         // padded row stride bytes (136 halves)
#define TILE_HB (M_TILE * ROW_B)    // 17408: one 64x128 fp16 tile
#define W_B     (128 * ROW_B)       // 34816: 128x128 fp16 W tile

#define OFF_BIAS 0
#define OFF_MBAR 512
#define OFF_W    1024
#define OFF_X    (1024 + W_B)               // 35840
#define SMEM_TOTAL (OFF_X + 2 * TILE_HB)    // 70656 -> 2 CTAs/SM, 20 warps

// pre-converted W blocks: [b] -> 128x128 fp16 padded tile
__device__ __align__(16) char g_wcvt[NBLK * W_B];

__device__ __forceinline__ uint32_t smem_u32(const void* p) {
    uint32_t a;
    asm("{ .reg .u64 t; cvta.to.shared.u64 t, %1; cvt.u32.u64 %0, t; }" : "=r"(a) : "l"(p));
    return a;
}
__device__ __forceinline__ uint32_t pack_h2(float a, float b) {
    __half2 h = __float22half2_rn(make_float2(a, b));
    return *reinterpret_cast<uint32_t*>(&h);
}
__device__ __forceinline__ void ldsm_x4(uint32_t& r0, uint32_t& r1, uint32_t& r2, uint32_t& r3,
                                        uint32_t addr) {
    asm volatile("ldmatrix.sync.aligned.m8n8.x4.shared.b16 {%0,%1,%2,%3}, [%4];"
                 : "=r"(r0), "=r"(r1), "=r"(r2), "=r"(r3) : "r"(addr));
}
__device__ __forceinline__ void mma_f16(float* d, const uint32_t* a, uint32_t b0, uint32_t b1) {
    asm volatile(
        "mma.sync.aligned.m16n8k16.row.col.f32.f16.f16.f32 "
        "{%0,%1,%2,%3}, {%4,%5,%6,%7}, {%8,%9}, {%0,%1,%2,%3};"
        : "+f"(d[0]), "+f"(d[1]), "+f"(d[2]), "+f"(d[3])
        : "r"(a[0]), "r"(a[1]), "r"(a[2]), "r"(a[3]), "r"(b0), "r"(b1));
}
__device__ __forceinline__ float wire_act(float z) {
    float s, e;
    asm("sin.approx.ftz.f32 %0, %1;" : "=f"(s) : "f"(z * 30.0f));
    float t = -0.01442695040888963f * z * z;   // -0.01 * log2(e) * z^2
    asm("ex2.approx.ftz.f32 %0, %1;" : "=f"(e) : "f"(t));
    return s * e;
}

#define MBAR_INIT(mb, c) asm volatile("mbarrier.init.shared.b64 [%0], %1;" :: "r"(mb), "r"((uint32_t)(c)) : "memory")
#define MBAR_ARRIVE(mb)  asm volatile("mbarrier.arrive.shared.b64 _, [%0];" :: "r"(mb) : "memory")
__device__ __forceinline__ void mbar_wait(uint32_t mb, uint32_t parity) {
    uint32_t done = 0;
    while (!done) {
        asm volatile(
            "{\n\t.reg .pred p;\n\t"
            "mbarrier.try_wait.parity.acquire.cta.shared::cta.b64 p, [%1], %2, 0x989680;\n\t"
            "selp.b32 %0, 1, 0, p;\n\t}"
            : "=r"(done) : "r"(mb), "r"(parity) : "memory");
    }
}

// ------------- prep: convert W diag blocks to fp16 padded tiles -------------
__global__ void __launch_bounds__(128)
wcvt_kernel(const float* __restrict__ w)
{
    const int b = blockIdx.x;
    const int t = threadIdx.x;
    const int r0 = t >> 5;
    const int c4 = t & 31;
    const float* wrow = w + (size_t)(b * 128) * IN_F + (size_t)b * 128;
    char* dst = g_wcvt + (size_t)b * W_B;
    #pragma unroll 4
    for (int r = r0; r < 128; r += 4) {
        float4 v = *(const float4*)(wrow + (size_t)r * IN_F + (c4 << 2));
        uint32_t h01 = pack_h2(v.x, v.y);
        uint32_t h23 = pack_h2(v.z, v.w);
        *(uint2*)(dst + r * ROW_B + (c4 << 3)) = make_uint2(h01, h23);
    }
}

// ------------- main kernel: warp-specialized pipelined GEMM -------------
__global__ void __launch_bounds__(320, 2)
siren_pipe1_kernel(const float* __restrict__ x, const float* __restrict__ bias,
                   float* __restrict__ out)
{
    extern __shared__ char smem[];
    const uint32_t sbase = smem_u32(smem);
    const int tid = threadIdx.x;
    const int wid = tid >> 5;
    const int lid = tid & 31;
    const int b = blockIdx.x;

    // mbarriers: full[s] (64 producer arrivals), empty[s] (256 consumer arrivals)
    if (tid == 0) {
        MBAR_INIT(sbase + OFF_MBAR + 0, 64);    // full0
        MBAR_INIT(sbase + OFF_MBAR + 8, 256);   // empty0
        MBAR_INIT(sbase + OFF_MBAR + 16, 64);   // full1
        MBAR_INIT(sbase + OFF_MBAR + 24, 256);  // empty1
    }
    __syncthreads();

    if (wid >= 8) {
        // ================= PRODUCER (warps 8,9 = 64 threads) =================
        const int pt = tid - 256;               // 0..63
        const int r0 = pt >> 5;                 // 0 or 1
        const int c4 = pt & 31;
        int stage = 0, phase = 1;
        #pragma unroll 1
        for (int i = 0; i < TPC; i++) {
            const int s = stage;
            mbar_wait(sbase + OFF_MBAR + s * 16 + 8, phase);
            const int row0 = (blockIdx.y * TPC + i) * M_TILE;
            const float* xp = x + (size_t)row0 * IN_F + (size_t)b * 128 + (c4 << 2);
            char* dst = smem + OFF_X + s * TILE_HB + (c4 << 3);
            #pragma unroll 1
            for (int jb = 0; jb < 4; jb++) {
                float4 v[8];
                #pragma unroll
                for (int u = 0; u < 8; u++) {
                    const int r = r0 + 2 * (jb * 8 + u);
                    v[u] = *(const float4*)(xp + (size_t)r * IN_F);
                }
                #pragma unroll
                for (int u = 0; u < 8; u++) {
                    const int r = r0 + 2 * (jb * 8 + u);
                    *(uint2*)(dst + r * ROW_B) =
                        make_uint2(pack_h2(v[u].x, v[u].y), pack_h2(v[u].z, v[u].w));
                }
            }
            MBAR_ARRIVE(sbase + OFF_MBAR + s * 16);   // full[s]
            if (++stage == 2) { stage = 0; phase ^= 1; }
        }
    } else {
        // ================= CONSUMER (warps 0-7 = 256 threads) =================
        {
            const char* wsrc = g_wcvt + (size_t)b * W_B;
            #pragma unroll 8
            for (int i = tid; i < W_B / 16; i += 256) {
                uint32_t dst = sbase + OFF_W + i * 16;
                asm volatile("cp.async.cg.shared.global [%0], [%1], 16;"
                             :: "r"(dst), "l"(wsrc + i * 16) : "memory");
            }
            asm volatile("cp.async.commit_group;" ::: "memory");
            if (tid < 128) ((float*)(smem + OFF_BIAS))[tid] = bias[b * 128 + tid];
            asm volatile("cp.async.wait_group 0;" ::: "memory");
            asm volatile("bar.sync 1, 256;" ::: "memory");   // consumer-only barrier
        }

        const int warp_m = wid & 3;          // m16 slice
        const int warp_n = wid >> 2;         // n64 slice
        const int M0 = warp_m * 16;
        const int N0 = warp_n * 64;
        const uint32_t offA = (uint32_t)((lid & 15) * ROW_B + (lid >> 4) * 16);
        const uint32_t offB = (uint32_t)((((lid >> 4) & 1) * 8 + (lid & 7)) * ROW_B
                                         + ((lid >> 3) & 1) * 16);
        const uint32_t bB = sbase + OFF_W + (uint32_t)(N0 * ROW_B) + offB;
        const float* bs = (const float*)(smem + OFF_BIAS);
        const int lrow = lid >> 2;
        const int lcol = (lid & 3) * 2;

        int stage = 0, phase = 0;
        #pragma unroll 1
        for (int i = 0; i < TPC; i++) {
            const int s = stage;
            mbar_wait(sbase + OFF_MBAR + s * 16, phase);   // full[s]

            const uint32_t aB = sbase + OFF_X + s * TILE_HB + (uint32_t)(M0 * ROW_B) + offA;

            float acc[8][4];
            #pragma unroll
            for (int nt = 0; nt < 8; nt++)
                #pragma unroll
                for (int k = 0; k < 4; k++) acc[nt][k] = 0.0f;

            #pragma unroll
            for (int ks = 0; ks < 8; ks++) {
                const uint32_t kb = (uint32_t)(ks * 32);
                uint32_t af[4];
                ldsm_x4(af[0], af[1], af[2], af[3], aB + kb);
                uint32_t bf[4][4];
                #pragma unroll
                for (int nt4 = 0; nt4 < 4; nt4++)
                    ldsm_x4(bf[nt4][0], bf[nt4][1], bf[nt4][2], bf[nt4][3],
                            bB + kb + (uint32_t)(nt4 * 16 * ROW_B));
                #pragma unroll
                for (int nt = 0; nt < 8; nt++)
                    mma_f16(acc[nt], af, bf[nt >> 1][(nt & 1) * 2], bf[nt >> 1][(nt & 1) * 2 + 1]);
            }
            MBAR_ARRIVE(sbase + OFF_MBAR + s * 16 + 8);    // empty[s] — free buffer early

            // epilogue: bias + wire activation + store
            const int row0 = (blockIdx.y * TPC + i) * M_TILE;
            const int rbase = row0 + M0 + lrow;
            #pragma unroll
            for (int nt = 0; nt < 8; nt++) {
                const int nn = N0 + nt * 8 + lcol;
                float* p0 = out + (size_t)rbase * OUT_F + (size_t)b * 128 + nn;
                float2 v0, v1;
                v0.x = wire_act(acc[nt][0] + bs[nn]);
                v0.y = wire_act(acc[nt][1] + bs[nn + 1]);
                v1.x = wire_act(acc[nt][2] + bs[nn]);
                v1.y = wire_act(acc[nt][3] + bs[nn + 1]);
                *(float2*)p0 = v0;
                *(float2*)(p0 + (size_t)8 * OUT_F) = v1;
            }
            if (++stage == 2) { stage = 0; phase ^= 1; }
        }
    }
}

extern "C" void kernel_launch(void* const* d_in, const int* in_sizes, int n_in,
                              void* d_out, int out_size)
{
    const float* x    = (const float*)d_in[0];
    const float* w    = (const float*)d_in[1];
    const float* bias = (const float*)d_in[2];
    float* out = (float*)d_out;

    wcvt_kernel<<<NBLK, 128>>>(w);

    cudaFuncSetAttribute(siren_pipe1_kernel,
                         cudaFuncAttributeMaxDynamicSharedMemorySize, SMEM_TOTAL);
    dim3 grid(NBLK, GRID_Y);
    siren_pipe1_kernel<<<grid, 320, SMEM_TOTAL>>>(x, bias, out);
}

// round 8
// speedup vs baseline: 1.9081x; 1.1368x over previous
#include <cuda_runtime.h>
#include <cuda_fp16.h>
#include <cstdint>

#define IN_F   8192
#define OUT_F  8192
#define NBLK   64
#define M_TILE 64
#define TPC    8            // tiles per CTA
#define GRID_Y 16           // 16*8 tiles * 64 rows = 8192 tokens

#define ROW_B   272         // padded row stride bytes (136 halves)
#define TILE_HB (M_TILE * ROW_B)    // 17408: one 64x128 fp16 tile
#define W_B     (128 * ROW_B)       // 34816: 128x128 fp16 W tile

#define OFF_BIAS 0
#define OFF_MBAR 512
#define OFF_W    1024
#define OFF_X    (1024 + W_B)               // 35840
#define SMEM_TOTAL (OFF_X + 2 * TILE_HB)    // 70656 -> 3 CTAs/SM (212KB), 30 warps

// pre-converted W blocks: [b] -> 128x128 fp16 padded tile
__device__ __align__(16) char g_wcvt[NBLK * W_B];

__device__ __forceinline__ uint32_t smem_u32(const void* p) {
    uint32_t a;
    asm("{ .reg .u64 t; cvta.to.shared.u64 t, %1; cvt.u32.u64 %0, t; }" : "=r"(a) : "l"(p));
    return a;
}
__device__ __forceinline__ uint32_t pack_h2(float a, float b) {
    __half2 h = __float22half2_rn(make_float2(a, b));
    return *reinterpret_cast<uint32_t*>(&h);
}
__device__ __forceinline__ void ldsm_x4(uint32_t& r0, uint32_t& r1, uint32_t& r2, uint32_t& r3,
                                        uint32_t addr) {
    asm volatile("ldmatrix.sync.aligned.m8n8.x4.shared.b16 {%0,%1,%2,%3}, [%4];"
                 : "=r"(r0), "=r"(r1), "=r"(r2), "=r"(r3) : "r"(addr));
}
__device__ __forceinline__ void mma_f16(float* d, const uint32_t* a, uint32_t b0, uint32_t b1) {
    asm volatile(
        "mma.sync.aligned.m16n8k16.row.col.f32.f16.f16.f32 "
        "{%0,%1,%2,%3}, {%4,%5,%6,%7}, {%8,%9}, {%0,%1,%2,%3};"
        : "+f"(d[0]), "+f"(d[1]), "+f"(d[2]), "+f"(d[3])
        : "r"(a[0]), "r"(a[1]), "r"(a[2]), "r"(a[3]), "r"(b0), "r"(b1));
}
__device__ __forceinline__ float wire_act(float z) {
    float s, e;
    asm("sin.approx.ftz.f32 %0, %1;" : "=f"(s) : "f"(z * 30.0f));
    float t = -0.01442695040888963f * z * z;   // -0.01 * log2(e) * z^2
    asm("ex2.approx.ftz.f32 %0, %1;" : "=f"(e) : "f"(t));
    return s * e;
}

#define MBAR_INIT(mb, c) asm volatile("mbarrier.init.shared.b64 [%0], %1;" :: "r"(mb), "r"((uint32_t)(c)) : "memory")
#define MBAR_ARRIVE(mb)  asm volatile("mbarrier.arrive.shared.b64 _, [%0];" :: "r"(mb) : "memory")
__device__ __forceinline__ void mbar_wait(uint32_t mb, uint32_t parity) {
    uint32_t done = 0;
    while (!done) {
        asm volatile(
            "{\n\t.reg .pred p;\n\t"
            "mbarrier.try_wait.parity.acquire.cta.shared::cta.b64 p, [%1], %2, 0x989680;\n\t"
            "selp.b32 %0, 1, 0, p;\n\t}"
            : "=r"(done) : "r"(mb), "r"(parity) : "memory");
    }
}

// ------------- prep: convert W diag blocks to fp16 padded tiles -------------
__global__ void __launch_bounds__(128)
wcvt_kernel(const float* __restrict__ w)
{
    const int b = blockIdx.x;
    const int t = threadIdx.x;
    const int r0 = t >> 5;
    const int c4 = t & 31;
    const float* wrow = w + (size_t)(b * 128) * IN_F + (size_t)b * 128;
    char* dst = g_wcvt + (size_t)b * W_B;
    #pragma unroll 4
    for (int r = r0; r < 128; r += 4) {
        float4 v = *(const float4*)(wrow + (size_t)r * IN_F + (c4 << 2));
        uint32_t h01 = pack_h2(v.x, v.y);
        uint32_t h23 = pack_h2(v.z, v.w);
        *(uint2*)(dst + r * ROW_B + (c4 << 3)) = make_uint2(h01, h23);
    }
}

// ------------- main kernel: warp-specialized pipelined GEMM -------------
__global__ void __launch_bounds__(320, 3)
siren_pipe1_kernel(const float* __restrict__ x, const float* __restrict__ bias,
                   float* __restrict__ out)
{
    extern __shared__ char smem[];
    const uint32_t sbase = smem_u32(smem);
    const int tid = threadIdx.x;
    const int wid = tid >> 5;
    const int lid = tid & 31;
    const int b = blockIdx.x;

    // mbarriers: full[s] (64 producer arrivals), empty[s] (256 consumer arrivals)
    if (tid == 0) {
        MBAR_INIT(sbase + OFF_MBAR + 0, 64);    // full0
        MBAR_INIT(sbase + OFF_MBAR + 8, 256);   // empty0
        MBAR_INIT(sbase + OFF_MBAR + 16, 64);   // full1
        MBAR_INIT(sbase + OFF_MBAR + 24, 256);  // empty1
    }
    __syncthreads();

    if (wid >= 8) {
        // ================= PRODUCER (warps 8,9 = 64 threads) =================
        const int pt = tid - 256;               // 0..63
        const int r0 = pt >> 5;                 // 0 or 1
        const int c4 = pt & 31;
        int stage = 0, phase = 1;
        #pragma unroll 1
        for (int i = 0; i < TPC; i++) {
            const int s = stage;
            mbar_wait(sbase + OFF_MBAR + s * 16 + 8, phase);
            const int row0 = (blockIdx.y * TPC + i) * M_TILE;
            const float* xp = x + (size_t)row0 * IN_F + (size_t)b * 128 + (c4 << 2);
            char* dst = smem + OFF_X + s * TILE_HB + (c4 << 3);
            #pragma unroll 1
            for (int jb = 0; jb < 4; jb++) {
                float4 v[8];
                #pragma unroll
                for (int u = 0; u < 8; u++) {
                    const int r = r0 + 2 * (jb * 8 + u);
                    v[u] = *(const float4*)(xp + (size_t)r * IN_F);
                }
                #pragma unroll
                for (int u = 0; u < 8; u++) {
                    const int r = r0 + 2 * (jb * 8 + u);
                    *(uint2*)(dst + r * ROW_B) =
                        make_uint2(pack_h2(v[u].x, v[u].y), pack_h2(v[u].z, v[u].w));
                }
            }
            MBAR_ARRIVE(sbase + OFF_MBAR + s * 16);   // full[s]
            if (++stage == 2) { stage = 0; phase ^= 1; }
        }
    } else {
        // ================= CONSUMER (warps 0-7 = 256 threads) =================
        {
            const char* wsrc = g_wcvt + (size_t)b * W_B;
            #pragma unroll 8
            for (int i = tid; i < W_B / 16; i += 256) {
                uint32_t dst = sbase + OFF_W + i * 16;
                asm volatile("cp.async.cg.shared.global [%0], [%1], 16;"
                             :: "r"(dst), "l"(wsrc + i * 16) : "memory");
            }
            asm volatile("cp.async.commit_group;" ::: "memory");
            if (tid < 128) ((float*)(smem + OFF_BIAS))[tid] = bias[b * 128 + tid];
            asm volatile("cp.async.wait_group 0;" ::: "memory");
            asm volatile("bar.sync 1, 256;" ::: "memory");   // consumer-only barrier
        }

        const int warp_m = wid & 3;          // m16 slice
        const int warp_n = wid >> 2;         // n64 slice
        const int M0 = warp_m * 16;
        const int N0 = warp_n * 64;
        const uint32_t offA = (uint32_t)((lid & 15) * ROW_B + (lid >> 4) * 16);
        const uint32_t offB = (uint32_t)((((lid >> 4) & 1) * 8 + (lid & 7)) * ROW_B
                                         + ((lid >> 3) & 1) * 16);
        const uint32_t bB = sbase + OFF_W + (uint32_t)(N0 * ROW_B) + offB;
        const float* bs = (const float*)(smem + OFF_BIAS);
        const int lrow = lid >> 2;
        const int lcol = (lid & 3) * 2;

        int stage = 0, phase = 0;
        #pragma unroll 1
        for (int i = 0; i < TPC; i++) {
            const int s = stage;
            mbar_wait(sbase + OFF_MBAR + s * 16, phase);   // full[s]

            const uint32_t aB = sbase + OFF_X + s * TILE_HB + (uint32_t)(M0 * ROW_B) + offA;

            float acc[8][4];
            #pragma unroll
            for (int nt = 0; nt < 8; nt++)
                #pragma unroll
                for (int k = 0; k < 4; k++) acc[nt][k] = 0.0f;

            #pragma unroll
            for (int ks = 0; ks < 8; ks++) {
                const uint32_t kb = (uint32_t)(ks * 32);
                uint32_t af[4];
                ldsm_x4(af[0], af[1], af[2], af[3], aB + kb);
                #pragma unroll
                for (int nt4 = 0; nt4 < 4; nt4++) {
                    uint32_t bq[4];
                    ldsm_x4(bq[0], bq[1], bq[2], bq[3],
                            bB + kb + (uint32_t)(nt4 * 16 * ROW_B));
                    mma_f16(acc[nt4 * 2 + 0], af, bq[0], bq[1]);
                    mma_f16(acc[nt4 * 2 + 1], af, bq[2], bq[3]);
                }
            }
            MBAR_ARRIVE(sbase + OFF_MBAR + s * 16 + 8);    // empty[s] — free buffer early

            // epilogue: bias + wire activation + store
            const int row0 = (blockIdx.y * TPC + i) * M_TILE;
            const int rbase = row0 + M0 + lrow;
            #pragma unroll
            for (int nt = 0; nt < 8; nt++) {
                const int nn = N0 + nt * 8 + lcol;
                float* p0 = out + (size_t)rbase * OUT_F + (size_t)b * 128 + nn;
                float2 v0, v1;
                v0.x = wire_act(acc[nt][0] + bs[nn]);
                v0.y = wire_act(acc[nt][1] + bs[nn + 1]);
                v1.x = wire_act(acc[nt][2] + bs[nn]);
                v1.y = wire_act(acc[nt][3] + bs[nn + 1]);
                *(float2*)p0 = v0;
                *(float2*)(p0 + (size_t)8 * OUT_F) = v1;
            }
            if (++stage == 2) { stage = 0; phase ^= 1; }
        }
    }
}

extern "C" void kernel_launch(void* const* d_in, const int* in_sizes, int n_in,
                              void* d_out, int out_size)
{
    const float* x    = (const float*)d_in[0];
    const float* w    = (const float*)d_in[1];
    const float* bias = (const float*)d_in[2];
    float* out = (float*)d_out;

    wcvt_kernel<<<NBLK, 128>>>(w);

    cudaFuncSetAttribute(siren_pipe1_kernel,
                         cudaFuncAttributeMaxDynamicSharedMemorySize, SMEM_TOTAL);
    dim3 grid(NBLK, GRID_Y);
    siren_pipe1_kernel<<<grid, 320, SMEM_TOTAL>>>(x, bias, out);
}

// round 11
// speedup vs baseline: 2.0950x; 1.0979x over previous
#include <cuda_runtime.h>
#include <cuda_fp16.h>
#include <cstdint>

#define IN_F   8192
#define OUT_F  8192
#define NBLK   64
#define M_TILE 32
#define GRID_Y 16
#define T_TILES 16          // 8192 / GRID_Y / M_TILE

#define ROW_B   272         // W fp16 padded row stride bytes
#define W_B     (128 * ROW_B)       // 34816
#define XROW_B  544                 // fp32 X padded row stride bytes (136 floats)
#define XSTG    (M_TILE * XROW_B)   // 17408 per stage

#define OFF_BIAS 0
#define OFF_W    1024
#define OFF_X    (1024 + W_B)               // 35840
#define SMEM_TOTAL (OFF_X + 2 * XSTG)       // 70656 -> 3 CTAs/SM

// pre-converted W blocks: [b] -> 128x128 fp16 padded tile
__device__ __align__(16) char g_wcvt[NBLK * W_B];

__device__ __forceinline__ uint32_t smem_u32(const void* p) {
    uint32_t a;
    asm("{ .reg .u64 t; cvta.to.shared.u64 t, %1; cvt.u32.u64 %0, t; }" : "=r"(a) : "l"(p));
    return a;
}
__device__ __forceinline__ uint32_t pack_h2(float a, float b) {
    __half2 h = __float22half2_rn(make_float2(a, b));
    return *reinterpret_cast<uint32_t*>(&h);
}
__device__ __forceinline__ float2 lds64(uint32_t a) {
    float2 v;
    asm volatile("ld.shared.v2.f32 {%0,%1}, [%2];" : "=f"(v.x), "=f"(v.y) : "r"(a));
    return v;
}
__device__ __forceinline__ void ldsm_x4(uint32_t& r0, uint32_t& r1, uint32_t& r2, uint32_t& r3,
                                        uint32_t addr) {
    asm volatile("ldmatrix.sync.aligned.m8n8.x4.shared.b16 {%0,%1,%2,%3}, [%4];"
                 : "=r"(r0), "=r"(r1), "=r"(r2), "=r"(r3) : "r"(addr));
}
__device__ __forceinline__ void mma_f16(float* d, const uint32_t* a, uint32_t b0, uint32_t b1) {
    asm volatile(
        "mma.sync.aligned.m16n8k16.row.col.f32.f16.f16.f32 "
        "{%0,%1,%2,%3}, {%4,%5,%6,%7}, {%8,%9}, {%0,%1,%2,%3};"
        : "+f"(d[0]), "+f"(d[1]), "+f"(d[2]), "+f"(d[3])
        : "r"(a[0]), "r"(a[1]), "r"(a[2]), "r"(a[3]), "r"(b0), "r"(b1));
}
__device__ __forceinline__ float wire_act(float z) {
    float s, e;
    asm("sin.approx.ftz.f32 %0, %1;" : "=f"(s) : "f"(z * 30.0f));
    float t = -0.01442695040888963f * z * z;   // -0.01 * log2(e) * z^2
    asm("ex2.approx.ftz.f32 %0, %1;" : "=f"(e) : "f"(t));
    return s * e;
}

// ------------- prep: convert W diag blocks to fp16 padded tiles -------------
__global__ void __launch_bounds__(128)
wcvt_kernel(const float* __restrict__ w)
{
    const int b = blockIdx.x;
    const int t = threadIdx.x;
    const int r0 = t >> 5;
    const int c4 = t & 31;
    const float* wrow = w + (size_t)(b * 128) * IN_F + (size_t)b * 128;
    char* dst = g_wcvt + (size_t)b * W_B;
    #pragma unroll 4
    for (int r = r0; r < 128; r += 4) {
        float4 v = *(const float4*)(wrow + (size_t)r * IN_F + (c4 << 2));
        *(uint2*)(dst + r * ROW_B + (c4 << 3)) =
            make_uint2(pack_h2(v.x, v.y), pack_h2(v.z, v.w));
    }
}

// ------------- main kernel: multistage cp.async, all warps compute -------------
__global__ void __launch_bounds__(256, 3)
siren_async_kernel(const float* __restrict__ x, const float* __restrict__ bias,
                   float* __restrict__ out)
{
    extern __shared__ char smem[];
    const uint32_t sbase = smem_u32(smem);
    const int tid = threadIdx.x;
    const int wid = tid >> 5;
    const int lid = tid & 31;
    const int b = blockIdx.x;
    const int row_base = blockIdx.y * (T_TILES * M_TILE);

    // ---- W tile (group 0) ----
    {
        const char* wsrc = g_wcvt + (size_t)b * W_B;
        #pragma unroll 9
        for (int i = tid; i < W_B / 16; i += 256) {
            uint32_t dst = sbase + OFF_W + i * 16;
            asm volatile("cp.async.cg.shared.global [%0], [%1], 16;"
                         :: "r"(dst), "l"(wsrc + i * 16) : "memory");
        }
        asm volatile("cp.async.commit_group;" ::: "memory");
    }
    if (tid < 128) ((float*)(smem + OFF_BIAS))[tid] = bias[b * 128 + tid];

    // ---- X stage issue helper (inline twice in prologue, once in loop) ----
    const float* xbase = x + (size_t)row_base * IN_F + (size_t)b * 128;
    #define ISSUE_X(t_, buf_)                                                     \
        {                                                                         \
            const float* src_ = xbase + (size_t)((t_) * M_TILE) * IN_F;           \
            const uint32_t db_ = sbase + OFF_X + (buf_) * XSTG;                   \
            _Pragma("unroll")                                                     \
            for (int j_ = 0; j_ < 4; j_++) {                                      \
                int c_ = tid + j_ * 256;                                          \
                int r_ = c_ >> 5, o_ = c_ & 31;                                   \
                asm volatile("cp.async.cg.shared.global [%0], [%1], 16;"          \
                             :: "r"(db_ + r_ * XROW_B + o_ * 16),                 \
                                "l"(src_ + (size_t)r_ * IN_F + o_ * 4) : "memory"); \
            }                                                                     \
        }

    ISSUE_X(0, 0);
    asm volatile("cp.async.commit_group;" ::: "memory");
    ISSUE_X(1, 1);
    asm volatile("cp.async.commit_group;" ::: "memory");

    // ---- warp tiling: 8 warps -> 2 (m16) x 4 (n32) ----
    const int M0 = (wid & 1) * 16;
    const int N0 = (wid >> 1) * 32;
    const uint32_t offB = (uint32_t)((((lid >> 4) & 1) * 8 + (lid & 7)) * ROW_B
                                     + ((lid >> 3) & 1) * 16);
    const uint32_t bB = sbase + OFF_W + (uint32_t)(N0 * ROW_B) + offB;
    const uint32_t aoff = (uint32_t)((M0 + (lid >> 2)) * XROW_B + (lid & 3) * 8);
    const float* bs = (const float*)(smem + OFF_BIAS);
    const int lrow = lid >> 2;
    const int lcol = (lid & 3) * 2;

    #pragma unroll 1
    for (int t = 0; t < T_TILES; t++) {
        asm volatile("cp.async.wait_group 1;" ::: "memory");
        __syncthreads();

        const uint32_t aS = sbase + OFF_X + (t & 1) * XSTG + aoff;

        float acc[4][4];
        #pragma unroll
        for (int nt = 0; nt < 4; nt++)
            #pragma unroll
            for (int k = 0; k < 4; k++) acc[nt][k] = 0.0f;

        #pragma unroll
        for (int ks = 0; ks < 8; ks++) {
            const uint32_t ka = (uint32_t)(ks * 64);   // 16 floats
            float2 A0 = lds64(aS + ka);
            float2 A1 = lds64(aS + ka + 8 * XROW_B);
            float2 A2 = lds64(aS + ka + 32);
            float2 A3 = lds64(aS + ka + 8 * XROW_B + 32);
            uint32_t af[4];
            af[0] = pack_h2(A0.x, A0.y);
            af[1] = pack_h2(A1.x, A1.y);
            af[2] = pack_h2(A2.x, A2.y);
            af[3] = pack_h2(A3.x, A3.y);
            const uint32_t kb = (uint32_t)(ks * 32);   // 16 halves
            #pragma unroll
            for (int nt4 = 0; nt4 < 2; nt4++) {
                uint32_t bq[4];
                ldsm_x4(bq[0], bq[1], bq[2], bq[3],
                        bB + kb + (uint32_t)(nt4 * 16 * ROW_B));
                mma_f16(acc[nt4 * 2 + 0], af, bq[0], bq[1]);
                mma_f16(acc[nt4 * 2 + 1], af, bq[2], bq[3]);
            }
        }

        __syncthreads();                     // all warps done reading buf (t&1)
        if (t + 2 < T_TILES) ISSUE_X(t + 2, t & 1);
        asm volatile("cp.async.commit_group;" ::: "memory");

        // ---- epilogue: bias + wire activation + store (overlaps next loads) ----
        const int rbase = row_base + t * M_TILE + M0 + lrow;
        #pragma unroll
        for (int nt = 0; nt < 4; nt++) {
            const int nn = N0 + nt * 8 + lcol;
            float* p0 = out + (size_t)rbase * OUT_F + (size_t)b * 128 + nn;
            float2 v0, v1;
            v0.x = wire_act(acc[nt][0] + bs[nn]);
            v0.y = wire_act(acc[nt][1] + bs[nn + 1]);
            v1.x = wire_act(acc[nt][2] + bs[nn]);
            v1.y = wire_act(acc[nt][3] + bs[nn + 1]);
            *(float2*)p0 = v0;
            *(float2*)(p0 + (size_t)8 * OUT_F) = v1;
        }
    }
}

extern "C" void kernel_launch(void* const* d_in, const int* in_sizes, int n_in,
                              void* d_out, int out_size)
{
    const float* x    = (const float*)d_in[0];
    const float* w    = (const float*)d_in[1];
    const float* bias = (const float*)d_in[2];
    float* out = (float*)d_out;

    wcvt_kernel<<<NBLK, 128>>>(w);

    cudaFuncSetAttribute(siren_async_kernel,
                         cudaFuncAttributeMaxDynamicSharedMemorySize, SMEM_TOTAL);
    dim3 grid(NBLK, GRID_Y);
    siren_async_kernel<<<grid, 256, SMEM_TOTAL>>>(x, bias, out);
}

// round 12
// speedup vs baseline: 2.4775x; 1.1826x over previous
#include <cuda_runtime.h>
#include <cuda_fp16.h>
#include <cstdint>

#define IN_F   8192
#define OUT_F  8192
#define NBLK   64
#define M_TILE 32
#define GRID_Y 16
#define T_TILES 16          // 8192 / GRID_Y / M_TILE

#define ROW_B   272                 // W fp16 padded row stride bytes
#define W_B     (128 * ROW_B)       // 34816
#define XROW_B  544                 // fp32 X padded row stride bytes (136 floats)
#define XSTG    (M_TILE * XROW_B)   // 17408 per stage
#define NSTAGE  3

#define OFF_BIAS 0
#define OFF_W    1024
#define OFF_X    (1024 + W_B)               // 35840
#define SMEM_TOTAL (OFF_X + NSTAGE * XSTG)  // 88064 -> 2 CTAs/SM

// pre-converted W blocks: [b] -> 128x128 fp16 padded tile
__device__ __align__(16) char g_wcvt[NBLK * W_B];

__device__ __forceinline__ uint32_t smem_u32(const void* p) {
    uint32_t a;
    asm("{ .reg .u64 t; cvta.to.shared.u64 t, %1; cvt.u32.u64 %0, t; }" : "=r"(a) : "l"(p));
    return a;
}
__device__ __forceinline__ uint32_t pack_h2(float a, float b) {
    __half2 h = __float22half2_rn(make_float2(a, b));
    return *reinterpret_cast<uint32_t*>(&h);
}
__device__ __forceinline__ float2 lds64(uint32_t a) {
    float2 v;
    asm volatile("ld.shared.v2.f32 {%0,%1}, [%2];" : "=f"(v.x), "=f"(v.y) : "r"(a));
    return v;
}
__device__ __forceinline__ void ldsm_x4(uint32_t& r0, uint32_t& r1, uint32_t& r2, uint32_t& r3,
                                        uint32_t addr) {
    asm volatile("ldmatrix.sync.aligned.m8n8.x4.shared.b16 {%0,%1,%2,%3}, [%4];"
                 : "=r"(r0), "=r"(r1), "=r"(r2), "=r"(r3) : "r"(addr));
}
__device__ __forceinline__ void mma_f16(float* d, const uint32_t* a, uint32_t b0, uint32_t b1) {
    asm volatile(
        "mma.sync.aligned.m16n8k16.row.col.f32.f16.f16.f32 "
        "{%0,%1,%2,%3}, {%4,%5,%6,%7}, {%8,%9}, {%0,%1,%2,%3};"
        : "+f"(d[0]), "+f"(d[1]), "+f"(d[2]), "+f"(d[3])
        : "r"(a[0]), "r"(a[1]), "r"(a[2]), "r"(a[3]), "r"(b0), "r"(b1));
}
__device__ __forceinline__ float wire_act(float z) {
    float s, e;
    asm("sin.approx.ftz.f32 %0, %1;" : "=f"(s) : "f"(z * 30.0f));
    float t = -0.01442695040888963f * z * z;   // -0.01 * log2(e) * z^2
    asm("ex2.approx.ftz.f32 %0, %1;" : "=f"(e) : "f"(t));
    return s * e;
}
__device__ __forceinline__ void stg_cs_v2(float* p, float a, float b) {
    asm volatile("st.global.cs.v2.f32 [%0], {%1,%2};" :: "l"(p), "f"(a), "f"(b) : "memory");
}

// ------------- prep: convert W diag blocks to fp16 padded tiles -------------
__global__ void __launch_bounds__(128)
wcvt_kernel(const float* __restrict__ w)
{
    const int b = blockIdx.x;
    const int t = threadIdx.x;
    const int r0 = t >> 5;
    const int c4 = t & 31;
    const float* wrow = w + (size_t)(b * 128) * IN_F + (size_t)b * 128;
    char* dst = g_wcvt + (size_t)b * W_B;
    #pragma unroll 4
    for (int r = r0; r < 128; r += 4) {
        float4 v = *(const float4*)(wrow + (size_t)r * IN_F + (c4 << 2));
        *(uint2*)(dst + r * ROW_B + (c4 << 3)) =
            make_uint2(pack_h2(v.x, v.y), pack_h2(v.z, v.w));
    }
}

// ------------- main kernel: B-in-registers, 3-stage cp.async X -------------
__global__ void __launch_bounds__(256, 2)
siren_breg_kernel(const float* __restrict__ x, const float* __restrict__ bias,
                  float* __restrict__ out)
{
    extern __shared__ char smem[];
    const uint32_t sbase = smem_u32(smem);
    const int tid = threadIdx.x;
    const int wid = tid >> 5;
    const int lid = tid & 31;
    const int b = blockIdx.x;
    const int row_base = blockIdx.y * (T_TILES * M_TILE);

    // ---- W tile via cp.async (group 0) ----
    {
        const char* wsrc = g_wcvt + (size_t)b * W_B;
        #pragma unroll 9
        for (int i = tid; i < W_B / 16; i += 256) {
            uint32_t dst = sbase + OFF_W + i * 16;
            asm volatile("cp.async.cg.shared.global [%0], [%1], 16;"
                         :: "r"(dst), "l"(wsrc + i * 16) : "memory");
        }
        asm volatile("cp.async.commit_group;" ::: "memory");
    }
    if (tid < 128) ((float*)(smem + OFF_BIAS))[tid] = bias[b * 128 + tid];

    const float* xbase = x + (size_t)row_base * IN_F + (size_t)b * 128;
    #define ISSUE_X(t_, buf_)                                                     \
        {                                                                         \
            const float* src_ = xbase + (size_t)((t_) * M_TILE) * IN_F;           \
            const uint32_t db_ = sbase + OFF_X + (buf_) * XSTG;                   \
            _Pragma("unroll")                                                     \
            for (int j_ = 0; j_ < 4; j_++) {                                      \
                int c_ = tid + j_ * 256;                                          \
                int r_ = c_ >> 5, o_ = c_ & 31;                                   \
                asm volatile("cp.async.cg.shared.global [%0], [%1], 16;"          \
                             :: "r"(db_ + r_ * XROW_B + o_ * 16),                 \
                                "l"(src_ + (size_t)r_ * IN_F + o_ * 4) : "memory"); \
            }                                                                     \
        }

    ISSUE_X(0, 0);
    asm volatile("cp.async.commit_group;" ::: "memory");
    ISSUE_X(1, 1);
    asm volatile("cp.async.commit_group;" ::: "memory");
    ISSUE_X(2, 2);
    asm volatile("cp.async.commit_group;" ::: "memory");

    // ---- warp tiling: 8 warps -> 2 (m16) x 4 (n32) ----
    const int M0 = (wid & 1) * 16;
    const int N0 = (wid >> 1) * 32;
    const uint32_t offB = (uint32_t)((((lid >> 4) & 1) * 8 + (lid & 7)) * ROW_B
                                     + ((lid >> 3) & 1) * 16);
    const uint32_t bB = sbase + OFF_W + (uint32_t)(N0 * ROW_B) + offB;
    const uint32_t aoff = (uint32_t)((M0 + (lid >> 2)) * XROW_B + (lid & 3) * 8);
    const float* bs = (const float*)(smem + OFF_BIAS);
    const int lrow = lid >> 2;
    const int lcol = (lid & 3) * 2;

    // ---- hoist all B fragments into registers (W constant across tiles) ----
    asm volatile("cp.async.wait_group 3;" ::: "memory");   // W retired
    __syncthreads();
    uint32_t breg[8][8];
    #pragma unroll
    for (int ks = 0; ks < 8; ks++) {
        const uint32_t kb = (uint32_t)(ks * 32);
        ldsm_x4(breg[ks][0], breg[ks][1], breg[ks][2], breg[ks][3], bB + kb);
        ldsm_x4(breg[ks][4], breg[ks][5], breg[ks][6], breg[ks][7],
                bB + kb + (uint32_t)(16 * ROW_B));
    }

    #pragma unroll 1
    for (int t = 0; t < T_TILES; t++) {
        asm volatile("cp.async.wait_group 2;" ::: "memory");   // X_t done
        __syncthreads();

        const int buf = t % NSTAGE;
        const uint32_t aS = sbase + OFF_X + buf * XSTG + aoff;

        float acc[4][4];
        #pragma unroll
        for (int nt = 0; nt < 4; nt++)
            #pragma unroll
            for (int k = 0; k < 4; k++) acc[nt][k] = 0.0f;

        #pragma unroll
        for (int ks = 0; ks < 8; ks++) {
            const uint32_t ka = (uint32_t)(ks * 64);   // 16 floats
            float2 A0 = lds64(aS + ka);
            float2 A1 = lds64(aS + ka + 8 * XROW_B);
            float2 A2 = lds64(aS + ka + 32);
            float2 A3 = lds64(aS + ka + 8 * XROW_B + 32);
            uint32_t af[4];
            af[0] = pack_h2(A0.x, A0.y);
            af[1] = pack_h2(A1.x, A1.y);
            af[2] = pack_h2(A2.x, A2.y);
            af[3] = pack_h2(A3.x, A3.y);
            mma_f16(acc[0], af, breg[ks][0], breg[ks][1]);
            mma_f16(acc[1], af, breg[ks][2], breg[ks][3]);
            mma_f16(acc[2], af, breg[ks][4], breg[ks][5]);
            mma_f16(acc[3], af, breg[ks][6], breg[ks][7]);
        }

        __syncthreads();                     // all warps done reading buf
        if (t + NSTAGE < T_TILES) ISSUE_X(t + NSTAGE, buf);
        asm volatile("cp.async.commit_group;" ::: "memory");

        // ---- epilogue: bias + wire activation + streaming store ----
        const int rbase = row_base + t * M_TILE + M0 + lrow;
        #pragma unroll
        for (int nt = 0; nt < 4; nt++) {
            const int nn = N0 + nt * 8 + lcol;
            float* p0 = out + (size_t)rbase * OUT_F + (size_t)b * 128 + nn;
            stg_cs_v2(p0, wire_act(acc[nt][0] + bs[nn]), wire_act(acc[nt][1] + bs[nn + 1]));
            stg_cs_v2(p0 + (size_t)8 * OUT_F,
                      wire_act(acc[nt][2] + bs[nn]), wire_act(acc[nt][3] + bs[nn + 1]));
        }
    }
}

extern "C" void kernel_launch(void* const* d_in, const int* in_sizes, int n_in,
                              void* d_out, int out_size)
{
    const float* x    = (const float*)d_in[0];
    const float* w    = (const float*)d_in[1];
    const float* bias = (const float*)d_in[2];
    float* out = (float*)d_out;

    wcvt_kernel<<<NBLK, 128>>>(w);

    cudaFuncSetAttribute(siren_breg_kernel,
                         cudaFuncAttributeMaxDynamicSharedMemorySize, SMEM_TOTAL);
    dim3 grid(NBLK, GRID_Y);
    siren_breg_kernel<<<grid, 256, SMEM_TOTAL>>>(x, bias, out);
}

// round 13
// speedup vs baseline: 2.4803x; 1.0012x over previous
#include <cuda_runtime.h>
#include <cuda_fp16.h>
#include <cstdint>

#define IN_F   8192
#define OUT_F  8192
#define NBLK   64
#define M_TILE 32
#define GRID_Y 9
#define TOT_TILES 256               // 8192 / 32 token tiles per feature block

#define ROW_B   272                 // W fp16 padded row stride bytes
#define W_B     (128 * ROW_B)       // 34816
#define XROW_B  544                 // fp32 X padded row stride bytes (136 floats)
#define XSTG    (M_TILE * XROW_B)   // 17408 per stage
#define NSTAGE  4

#define OFF_BIAS 0
#define OFF_W    1024
#define OFF_X    (1024 + W_B)               // 35840
#define SMEM_TOTAL (OFF_X + NSTAGE * XSTG)  // 105472 -> 2 CTAs/SM

// pre-converted W blocks: [b] -> 128x128 fp16 padded tile
__device__ __align__(16) char g_wcvt[NBLK * W_B];

__device__ __forceinline__ uint32_t smem_u32(const void* p) {
    uint32_t a;
    asm("{ .reg .u64 t; cvta.to.shared.u64 t, %1; cvt.u32.u64 %0, t; }" : "=r"(a) : "l"(p));
    return a;
}
__device__ __forceinline__ uint32_t pack_h2(float a, float b) {
    __half2 h = __float22half2_rn(make_float2(a, b));
    return *reinterpret_cast<uint32_t*>(&h);
}
__device__ __forceinline__ float2 lds64(uint32_t a) {
    float2 v;
    asm volatile("ld.shared.v2.f32 {%0,%1}, [%2];" : "=f"(v.x), "=f"(v.y) : "r"(a));
    return v;
}
__device__ __forceinline__ void ldsm_x4(uint32_t& r0, uint32_t& r1, uint32_t& r2, uint32_t& r3,
                                        uint32_t addr) {
    asm volatile("ldmatrix.sync.aligned.m8n8.x4.shared.b16 {%0,%1,%2,%3}, [%4];"
                 : "=r"(r0), "=r"(r1), "=r"(r2), "=r"(r3) : "r"(addr));
}
__device__ __forceinline__ void mma_f16(float* d, const uint32_t* a, uint32_t b0, uint32_t b1) {
    asm volatile(
        "mma.sync.aligned.m16n8k16.row.col.f32.f16.f16.f32 "
        "{%0,%1,%2,%3}, {%4,%5,%6,%7}, {%8,%9}, {%0,%1,%2,%3};"
        : "+f"(d[0]), "+f"(d[1]), "+f"(d[2]), "+f"(d[3])
        : "r"(a[0]), "r"(a[1]), "r"(a[2]), "r"(a[3]), "r"(b0), "r"(b1));
}
__device__ __forceinline__ float wire_act(float z) {
    float s, e;
    asm("sin.approx.ftz.f32 %0, %1;" : "=f"(s) : "f"(z * 30.0f));
    float t = -0.01442695040888963f * z * z;   // -0.01 * log2(e) * z^2
    asm("ex2.approx.ftz.f32 %0, %1;" : "=f"(e) : "f"(t));
    return s * e;
}
__device__ __forceinline__ void stg_cs_v2(float* p, float a, float b) {
    asm volatile("st.global.cs.v2.f32 [%0], {%1,%2};" :: "l"(p), "f"(a), "f"(b) : "memory");
}

// ------------- prep: convert W diag blocks to fp16 padded tiles -------------
__global__ void __launch_bounds__(128)
wcvt_kernel(const float* __restrict__ w)
{
    const int b = blockIdx.x;
    const int t = threadIdx.x;
    const int r0 = t >> 5;
    const int c4 = t & 31;
    const float* wrow = w + (size_t)(b * 128) * IN_F + (size_t)b * 128;
    char* dst = g_wcvt + (size_t)b * W_B;
    #pragma unroll 4
    for (int r = r0; r < 128; r += 4) {
        float4 v = *(const float4*)(wrow + (size_t)r * IN_F + (c4 << 2));
        *(uint2*)(dst + r * ROW_B + (c4 << 3)) =
            make_uint2(pack_h2(v.x, v.y), pack_h2(v.z, v.w));
    }
}

// ------------- main kernel: B-in-registers, 4-stage cp.async X -------------
__global__ void __launch_bounds__(256, 2)
siren_breg4_kernel(const float* __restrict__ x, const float* __restrict__ bias,
                   float* __restrict__ out)
{
    extern __shared__ char smem[];
    const uint32_t sbase = smem_u32(smem);
    const int tid = threadIdx.x;
    const int wid = tid >> 5;
    const int lid = tid & 31;
    const int b = blockIdx.x;

    // dynamic tile range for this CTA: tiles [tstart, tend) of 256
    const int yi = blockIdx.y;
    const int tstart = (TOT_TILES * yi) / GRID_Y;
    const int tend   = (TOT_TILES * (yi + 1)) / GRID_Y;
    const int ntiles = tend - tstart;

    // ---- W tile via cp.async (group 0) ----
    {
        const char* wsrc = g_wcvt + (size_t)b * W_B;
        #pragma unroll 9
        for (int i = tid; i < W_B / 16; i += 256) {
            uint32_t dst = sbase + OFF_W + i * 16;
            asm volatile("cp.async.cg.shared.global [%0], [%1], 16;"
                         :: "r"(dst), "l"(wsrc + i * 16) : "memory");
        }
        asm volatile("cp.async.commit_group;" ::: "memory");
    }
    if (tid < 128) ((float*)(smem + OFF_BIAS))[tid] = bias[b * 128 + tid];

    const float* xbase = x + (size_t)b * 128;
    // issue X tile (global tile index tj_) into ring buffer buf_
    #define ISSUE_X(tj_, buf_)                                                    \
        {                                                                         \
            const float* src_ = xbase + (size_t)((tj_) * M_TILE) * IN_F;          \
            const uint32_t db_ = sbase + OFF_X + (buf_) * XSTG;                   \
            _Pragma("unroll")                                                     \
            for (int j_ = 0; j_ < 4; j_++) {                                      \
                int c_ = tid + j_ * 256;                                          \
                int r_ = c_ >> 5, o_ = c_ & 31;                                   \
                asm volatile("cp.async.cg.shared.global [%0], [%1], 16;"          \
                             :: "r"(db_ + r_ * XROW_B + o_ * 16),                 \
                                "l"(src_ + (size_t)r_ * IN_F + o_ * 4) : "memory"); \
            }                                                                     \
        }

    #pragma unroll
    for (int p = 0; p < NSTAGE; p++) {
        ISSUE_X(tstart + p, p);            // ntiles >= 28 >> NSTAGE, always valid
        asm volatile("cp.async.commit_group;" ::: "memory");
    }

    // ---- warp tiling: 8 warps -> 2 (m16) x 4 (n32) ----
    const int M0 = (wid & 1) * 16;
    const int N0 = (wid >> 1) * 32;
    const uint32_t offB = (uint32_t)((((lid >> 4) & 1) * 8 + (lid & 7)) * ROW_B
                                     + ((lid >> 3) & 1) * 16);
    const uint32_t bB = sbase + OFF_W + (uint32_t)(N0 * ROW_B) + offB;
    const uint32_t aoff = (uint32_t)((M0 + (lid >> 2)) * XROW_B + (lid & 3) * 8);
    const float* bs = (const float*)(smem + OFF_BIAS);
    const int lrow = lid >> 2;
    const int lcol = (lid & 3) * 2;

    // ---- hoist all B fragments into registers (W constant across tiles) ----
    asm volatile("cp.async.wait_group %0;" :: "n"(NSTAGE) : "memory");   // W retired
    __syncthreads();
    uint32_t breg[8][8];
    #pragma unroll
    for (int ks = 0; ks < 8; ks++) {
        const uint32_t kb = (uint32_t)(ks * 32);
        ldsm_x4(breg[ks][0], breg[ks][1], breg[ks][2], breg[ks][3], bB + kb);
        ldsm_x4(breg[ks][4], breg[ks][5], breg[ks][6], breg[ks][7],
                bB + kb + (uint32_t)(16 * ROW_B));
    }

    #pragma unroll 1
    for (int i = 0; i < ntiles; i++) {
        asm volatile("cp.async.wait_group %0;" :: "n"(NSTAGE - 1) : "memory");  // X_i done
        __syncthreads();

        const int buf = i & (NSTAGE - 1);
        const uint32_t aS = sbase + OFF_X + buf * XSTG + aoff;

        float acc[4][4];
        #pragma unroll
        for (int nt = 0; nt < 4; nt++)
            #pragma unroll
            for (int k = 0; k < 4; k++) acc[nt][k] = 0.0f;

        #pragma unroll
        for (int ks = 0; ks < 8; ks++) {
            const uint32_t ka = (uint32_t)(ks * 64);   // 16 floats
            float2 A0 = lds64(aS + ka);
            float2 A1 = lds64(aS + ka + 8 * XROW_B);
            float2 A2 = lds64(aS + ka + 32);
            float2 A3 = lds64(aS + ka + 8 * XROW_B + 32);
            uint32_t af[4];
            af[0] = pack_h2(A0.x, A0.y);
            af[1] = pack_h2(A1.x, A1.y);
            af[2] = pack_h2(A2.x, A2.y);
            af[3] = pack_h2(A3.x, A3.y);
            mma_f16(acc[0], af, breg[ks][0], breg[ks][1]);
            mma_f16(acc[1], af, breg[ks][2], breg[ks][3]);
            mma_f16(acc[2], af, breg[ks][4], breg[ks][5]);
            mma_f16(acc[3], af, breg[ks][6], breg[ks][7]);
        }

        __syncthreads();                     // all warps done reading buf
        if (i + NSTAGE < ntiles) ISSUE_X(tstart + i + NSTAGE, buf);
        asm volatile("cp.async.commit_group;" ::: "memory");

        // ---- epilogue: bias + wire activation + streaming store ----
        const int rbase = (tstart + i) * M_TILE + M0 + lrow;
        #pragma unroll
        for (int nt = 0; nt < 4; nt++) {
            const int nn = N0 + nt * 8 + lcol;
            float* p0 = out + (size_t)rbase * OUT_F + (size_t)b * 128 + nn;
            stg_cs_v2(p0, wire_act(acc[nt][0] + bs[nn]), wire_act(acc[nt][1] + bs[nn + 1]));
            stg_cs_v2(p0 + (size_t)8 * OUT_F,
                      wire_act(acc[nt][2] + bs[nn]), wire_act(acc[nt][3] + bs[nn + 1]));
        }
    }
}

extern "C" void kernel_launch(void* const* d_in, const int* in_sizes, int n_in,
                              void* d_out, int out_size)
{
    const float* x    = (const float*)d_in[0];
    const float* w    = (const float*)d_in[1];
    const float* bias = (const float*)d_in[2];
    float* out = (float*)d_out;

    wcvt_kernel<<<NBLK, 128>>>(w);

    cudaFuncSetAttribute(siren_breg4_kernel,
                         cudaFuncAttributeMaxDynamicSharedMemorySize, SMEM_TOTAL);
    dim3 grid(NBLK, GRID_Y);
    siren_breg4_kernel<<<grid, 256, SMEM_TOTAL>>>(x, bias, out);
}